// round 1
// baseline (speedup 1.0000x reference)
#include <cuda_runtime.h>

#define N 256
#define NMASK 255
// volume per batch-channel
#define PLANE (N * N)            // 65536
#define VOL   (N * N * N)        // 16777216

// Block: 256 threads = 4 y-lines x 64 float4-quads (256 z each).
// Grid: b(4) * x(256) * ygroups(64) = 65536 blocks.
__global__ __launch_bounds__(256, 8)
void fd_grad_kernel(const float* __restrict__ v, float* __restrict__ out) {
    __shared__ float s[4 * N];

    const int t  = threadIdx.x;
    const int l  = t >> 6;          // line within block: 0..3
    const int q  = t & 63;          // float4 index along z: 0..63

    const unsigned bid = blockIdx.x;
    const int yb = bid & 63;              // y-group
    const int x  = (bid >> 6) & NMASK;    // x plane
    const int b  = bid >> 14;             // batch

    const int y  = (yb << 2) | l;         // this thread's y line

    const long long bvol = (long long)b * VOL;
    const float* __restrict__ basep = v + bvol + (long long)x * PLANE;

    // ---- center line load (also feeds gz) ----
    const float4* __restrict__ crow = (const float4*)(basep + (long long)y * N);
    float4 c = crow[q];

    // stash line in shared for the z-straddle elements
    ((float4*)(s + l * N))[q] = c;
    __syncthreads();

    const int zm = (4 * q - 1) & NMASK;   // element left of this quad
    const int zp = (4 * q + 4) & NMASK;   // element right of this quad
    const float sl = s[l * N + zm];
    const float sr = s[l * N + zp];

    float4 gz;
    gz.x = (c.y - sl)  * 0.5f;
    gz.y = (c.z - c.x) * 0.5f;
    gz.z = (c.w - c.y) * 0.5f;
    gz.w = (sr  - c.z) * 0.5f;

    // ---- y gradient: rows y+1, y-1 (periodic) ----
    const int yp = (y + 1) & NMASK;
    const int ym = (y - 1) & NMASK;
    float4 a  = ((const float4*)(basep + (long long)yp * N))[q];
    float4 d  = ((const float4*)(basep + (long long)ym * N))[q];
    float4 gy;
    gy.x = (a.x - d.x) * 0.5f;
    gy.y = (a.y - d.y) * 0.5f;
    gy.z = (a.z - d.z) * 0.5f;
    gy.w = (a.w - d.w) * 0.5f;

    // ---- x gradient: planes x+1, x-1 (periodic) ----
    const int xp = (x + 1) & NMASK;
    const int xm = (x - 1) & NMASK;
    const long long rowoff = (long long)y * N;
    float4 p = ((const float4*)(v + bvol + (long long)xp * PLANE + rowoff))[q];
    float4 m = ((const float4*)(v + bvol + (long long)xm * PLANE + rowoff))[q];
    float4 gx;
    gx.x = (p.x - m.x) * 0.5f;
    gx.y = (p.y - m.y) * 0.5f;
    gx.z = (p.z - m.z) * 0.5f;
    gx.w = (p.w - m.w) * 0.5f;

    // ---- stores: out[b][comp][x][y][z], comp: 0=gx, 1=gy, 2=gz ----
    float* __restrict__ ob = out + (long long)b * 3 * VOL
                                 + (long long)x * PLANE + rowoff;
    ((float4*)(ob            ))[q] = gx;
    ((float4*)(ob +       VOL))[q] = gy;
    ((float4*)(ob + 2LL * VOL))[q] = gz;
}

extern "C" void kernel_launch(void* const* d_in, const int* in_sizes, int n_in,
                              void* d_out, int out_size) {
    const float* v = (const float*)d_in[0];
    float* out = (float*)d_out;
    // 4 batches * 256 x-planes * 64 y-groups
    dim3 grid(4 * 256 * 64);
    dim3 block(256);
    fd_grad_kernel<<<grid, block>>>(v, out);
}